// round 7
// baseline (speedup 1.0000x reference)
#include <cuda_runtime.h>

#define B 8
#define HID 192
#define CATN 576
#define PIECES 64
#define HW 65536   // 256*256
#define PLANE3 (3*HW)
#define NBLK 148
#define NTHR 256

// ---------------- scratch (__device__ globals; allocation-free rule) --------
__device__ float  g_p1[4][4*B*HID];   // stage1 partials [isplit][(k*B+b)*HID+o]
__device__ float  g_p2[2][B*CATN];    // stage2 partials [isplit][b*CATN+sec*HID+o]
__device__ float  g_p3[3][B*HID];     // stage3 partials
__device__ float  g_p4[2][B*HID];     // stage4 partials
__device__ float2 g_table[B*9*PIECES];
__device__ unsigned g_s1, g_s2, g_s3, g_s4, g_s5, g_done;   // zero-init

// ---------------- flag sync --------------------------------------------------
__device__ __forceinline__ void wait_flag(unsigned* c, unsigned n) {
    if (threadIdx.x == 0) {
        while (*(volatile unsigned*)c < n) { }
        __threadfence();                 // gpu-scope fence -> drops stale L1
    }
    __syncthreads();
}
__device__ __forceinline__ void signal_flag(unsigned* c) {
    __threadfence();                     // drain my stores to L2
    __syncthreads();                     // all threads' stores drained
    if (threadIdx.x == 0) atomicAdd(c, 1u);
}

// ---------------- register-resident GEMV ------------------------------------
// Weights: lane l, warp w owns outputs obase+t*32+l, reduction rows w*CH+j.
template<int CH, int NT>
__device__ __forceinline__ void wload(float wreg[CH][NT], const float* __restrict__ W) {
    const int l = threadIdx.x & 31;
    const int w = threadIdx.x >> 5;
    const float* Wp = W + (w * CH) * HID + l;
    #pragma unroll
    for (int j = 0; j < CH; j++)
        #pragma unroll
        for (int t = 0; t < NT; t++)
            wreg[j][t] = Wp[j * HID + t * 32];
}

template<int CH, int NT, int RB>
__device__ __forceinline__ void gemv_reg(const float wreg[CH][NT],
                                         const float* __restrict__ sX,
                                         float acc[NT][B]) {
    const int w = threadIdx.x >> 5;
    #pragma unroll
    for (int j = 0; j < CH; j++)
        #pragma unroll
        for (int b = 0; b < B; b++) {
            float xv = sX[b * RB + w * CH + j];
            #pragma unroll
            for (int t = 0; t < NT; t++) acc[t][b] = fmaf(xv, wreg[j][t], acc[t][b]);
        }
}

template<int NT>
__device__ __forceinline__ void store_partials(float acc[NT][B], float* s_part,
                                               float* __restrict__ dst,
                                               int strideB, int obase) {
    const int OT = NT * 32;
    const int l = threadIdx.x & 31;
    const int w = threadIdx.x >> 5;
    #pragma unroll
    for (int t = 0; t < NT; t++)
        #pragma unroll
        for (int b = 0; b < B; b++)
            s_part[(w * B + b) * OT + t * 32 + l] = acc[t][b];
    __syncthreads();
    for (int p = threadIdx.x; p < OT * B; p += NTHR) {
        int b = p / OT, o = p % OT;
        float s = 0.0f;
        #pragma unroll
        for (int w2 = 0; w2 < 8; w2++) s += s_part[(w2 * B + b) * OT + o];
        dst[b * strideB + obase + o] = s;
    }
}

__device__ __forceinline__ void l2_prefetch(const void* p) {
    asm volatile("prefetch.global.L2 [%0];" :: "l"(p));
}

// ---------------- render helpers --------------------------------------------
__device__ __forceinline__ float evalp(float v, const float2* __restrict__ tab) {
    float s = v * 64.0f;
    int k = (int)s;
    k = min(k, 63);
    float frac = s - (float)k;
    float2 e = tab[k];
    return fmaf(frac, e.y, e.x);
}
__device__ __forceinline__ float4 eval4(float4 v, const float2* __restrict__ tab) {
    return make_float4(evalp(v.x, tab), evalp(v.y, tab), evalp(v.z, tab), evalp(v.w, tab));
}

// ---------------- the whole problem, one kernel -----------------------------
__global__ __launch_bounds__(NTHR) void fused_kernel(
    const float* __restrict__ x,
    const float* __restrict__ f_feat, const float* __restrict__ b_feat,
    const float* __restrict__ pw1, const float* __restrict__ pb1,
    const float* __restrict__ pw2, const float* __restrict__ pb2,
    const float* __restrict__ fw1, const float* __restrict__ fb1,
    const float* __restrict__ fw2, const float* __restrict__ fb2,
    float* __restrict__ out)
{
    __shared__ __align__(16) float s_buf[9216];   // 36 KB, reused per phase
    float* s_x    = s_buf;                        // activations (<=1536 floats)
    float* s_part = s_buf + 1536;                 // warp partials (<=6144)
    const int tid = threadIdx.x;
    const int blk = blockIdx.x;

    if (blk < 32) {
        // ===== stage 1: proj layer1. no wait; weights+feat load at t=0 ======
        int k  = blk >> 3;
        int oh = (blk >> 2) & 1;
        int ip = blk & 3;
        int ibase = ip * 128, obase = oh * 96;
        float wreg[16][3];
        wload<16, 3>(wreg, pw1 + (k * 512 + ibase) * HID + obase);
        const float* feat = (k & 1) ? b_feat : f_feat;
        for (int idx = tid; idx < B * 128; idx += NTHR)
            s_x[idx] = feat[(idx >> 7) * 512 + ibase + (idx & 127)];
        __syncthreads();
        float acc[3][B];
        #pragma unroll
        for (int t = 0; t < 3; t++)
            #pragma unroll
            for (int b = 0; b < B; b++) acc[t][b] = 0.0f;
        gemv_reg<16, 3, 128>(wreg, s_x, acc);
        store_partials<3>(acc, s_part, g_p1[ip] + (k * B) * HID, HID, obase);
        signal_flag(&g_s1);

    } else if (blk < 44) {
        // ===== stage 2: proj layer2 (waits s1==32) ==========================
        int local = blk - 32;
        int sec = local >> 2;
        int oh  = (local >> 1) & 1;
        int ip  = local & 1;
        int ibase = ip * 96, obase = oh * 96;
        int k0 = (sec == 2) ? 2 : sec;
        float wregA[12][3], wregB[12][3];
        wload<12, 3>(wregA, pw2 + (k0 * HID + ibase) * HID + obase);
        if (sec == 2)
            wload<12, 3>(wregB, pw2 + (3 * HID + ibase) * HID + obase);
        if (tid < 48) l2_prefetch(pb1 + tid * 16);           // bias warmup

        wait_flag(&g_s1, 32);
        int nk = (sec == 2) ? 2 : 1;
        for (int kk = 0; kk < nk; kk++) {
            int k = (sec == 2) ? (2 + kk) : sec;
            for (int idx = tid; idx < B * 96; idx += NTHR) {
                int b = idx / 96, i = idx % 96;
                int gi = (k * B + b) * HID + ibase + i;
                float v = g_p1[0][gi] + g_p1[1][gi] + g_p1[2][gi] + g_p1[3][gi]
                        + pb1[k * HID + ibase + i];
                s_x[kk * B * 96 + idx] = fmaxf(v, 0.0f);
            }
        }
        __syncthreads();
        float acc[3][B];
        #pragma unroll
        for (int t = 0; t < 3; t++)
            #pragma unroll
            for (int b = 0; b < B; b++) acc[t][b] = 0.0f;
        gemv_reg<12, 3, 96>(wregA, s_x, acc);
        if (sec == 2) gemv_reg<12, 3, 96>(wregB, s_x + B * 96, acc);
        store_partials<3>(acc, s_part, g_p2[ip], CATN, sec * HID + obase);
        signal_flag(&g_s2);

    } else if (blk < 53) {
        // ===== stage 3: fc layer1 (waits s2==12) ============================
        int local = blk - 44;
        int oq = local / 3, ip = local % 3;       // ip = cat section
        int obase = oq * 64;
        float wreg[24][2];
        wload<24, 2>(wreg, fw1 + (ip * HID) * HID + obase);
        if (tid < 48) l2_prefetch(pb2 + tid * 16);

        wait_flag(&g_s2, 12);
        for (int idx = tid; idx < B * 192; idx += NTHR) {
            int b = idx / 192, i = idx % 192;
            int gi = b * CATN + ip * HID + i;
            float v = g_p2[0][gi] + g_p2[1][gi];
            v += (ip < 2) ? pb2[ip * HID + i]
                          : (pb2[2 * HID + i] + pb2[3 * HID + i]);
            s_x[idx] = v;
        }
        __syncthreads();
        float acc[2][B];
        #pragma unroll
        for (int t = 0; t < 2; t++)
            #pragma unroll
            for (int b = 0; b < B; b++) acc[t][b] = 0.0f;
        gemv_reg<24, 2, 192>(wreg, s_x, acc);
        store_partials<2>(acc, s_part, g_p3[ip], HID, obase);
        signal_flag(&g_s3);

    } else if (blk < 57) {
        // ===== stage 4: fc layer2 (waits s3==9) =============================
        int local = blk - 53;
        int oh = local >> 1, ip = local & 1;
        int ibase = ip * 96, obase = oh * 96;
        float wreg[12][3];
        wload<12, 3>(wreg, fw2 + ibase * HID + obase);
        if (tid < 12) l2_prefetch(fb1 + tid * 16);

        wait_flag(&g_s3, 9);
        for (int idx = tid; idx < B * 96; idx += NTHR) {
            int b = idx / 96, i = idx % 96;
            int gi = b * HID + ibase + i;
            float v = g_p3[0][gi] + g_p3[1][gi] + g_p3[2][gi] + fb1[ibase + i];
            s_x[idx] = fmaxf(v, 0.0f);
        }
        __syncthreads();
        float acc[3][B];
        #pragma unroll
        for (int t = 0; t < 3; t++)
            #pragma unroll
            for (int b = 0; b < B; b++) acc[t][b] = 0.0f;
        gemv_reg<12, 3, 96>(wreg, s_x, acc);
        store_partials<3>(acc, s_part, g_p4[ip], HID, obase);
        signal_flag(&g_s4);

    } else if (blk < 66) {
        // ===== stage 5: lookup tables (waits s4==4; s2 implied) =============
        if (tid < 12) l2_prefetch(fb2 + tid * 16);
        wait_flag(&g_s4, 4);
        int l = tid & 31;
        int grp = (blk - 57) * 8 + (tid >> 5);    // 0..71
        int set = grp / 24;
        int b   = (grp % 24) / 3;
        int c   = grp % 3;
        int e0 = 2 * l, e1 = 2 * l + 1;
        float v0, v1;
        if (set == 0) {
            int gi = b * HID + c * 64;
            v0 = g_p4[0][gi + e0] + g_p4[1][gi + e0] + fb2[c * 64 + e0];
            v1 = g_p4[0][gi + e1] + g_p4[1][gi + e1] + fb2[c * 64 + e1];
        } else {
            int sec = set - 1;                    // param_f=0, param_b=1
            int gi = b * CATN + sec * HID + c * 64;
            v0 = g_p2[0][gi + e0] + g_p2[1][gi + e0] + pb2[sec * HID + c * 64 + e0];
            v1 = g_p2[0][gi + e1] + g_p2[1][gi + e1] + pb2[sec * HID + c * 64 + e1];
        }
        float pair = v0 + v1;
        float inc = pair;
        #pragma unroll
        for (int d = 1; d < 32; d <<= 1) {
            float u = __shfl_up_sync(0xffffffffu, inc, d);
            if (l >= d) inc += u;
        }
        float total = __shfl_sync(0xffffffffu, inc, 31);
        float excl  = inc - pair;
        float inv   = 1.0f / (total + 1e-30f);
        float2* t = &g_table[(b * 9 + set * 3 + c) * PIECES];
        t[e0] = make_float2(excl * inv, v0 * inv);
        t[e1] = make_float2((excl + v0) * inv, v1 * inv);
        signal_flag(&g_s5);

    } else {
        // ===== idle blocks: warm L2 with x while the MLP chain runs =========
        for (int i = (blk - 66) * NTHR + tid; i < (B * PLANE3) / 32; i += 82 * NTHR)
            l2_prefetch(x + i * 32);
    }

    // ===== final: render (everyone waits for tables) ========================
    wait_flag(&g_s5, 9);
    float2* s_tab = (float2*)s_buf;               // 72 tables = 36 KB
    for (int i = tid; i < B * 9 * PIECES; i += NTHR) s_tab[i] = g_table[i];
    __syncthreads();

    int gtid = blk * NTHR + tid;
    for (int p = gtid; p < B * HW / 4; p += NBLK * NTHR) {
        int b   = p >> 14;                        // HW/4 = 16384 per batch
        int off = (p & 16383) << 2;
        const float* xb = x + b * PLANE3 + off;
        float4 v0 = *(const float4*)(xb);
        float4 v1 = *(const float4*)(xb + HW);
        float4 v2 = *(const float4*)(xb + 2 * HW);

        float4 g;
        g.x = fmaf(0.114f, v2.x, fmaf(0.587f, v1.x, 0.299f * v0.x));
        g.y = fmaf(0.114f, v2.y, fmaf(0.587f, v1.y, 0.299f * v0.y));
        g.z = fmaf(0.114f, v2.z, fmaf(0.587f, v1.z, 0.299f * v0.z));
        g.w = fmaf(0.114f, v2.w, fmaf(0.587f, v1.w, 0.299f * v0.w));

        const float2* tb = s_tab + b * 9 * PIECES;

        float* o0 = out + b * PLANE3 + off;
        *(float4*)(o0)          = eval4(v0, tb + 0 * PIECES);
        *(float4*)(o0 + HW)     = eval4(v1, tb + 1 * PIECES);
        *(float4*)(o0 + 2 * HW) = eval4(v2, tb + 2 * PIECES);

        float* o1 = out + B * PLANE3 + b * PLANE3 + off;
        *(float4*)(o1)          = eval4(g, tb + 3 * PIECES);
        *(float4*)(o1 + HW)     = eval4(g, tb + 4 * PIECES);
        *(float4*)(o1 + 2 * HW) = eval4(g, tb + 5 * PIECES);

        float* o2 = out + 2 * B * PLANE3 + b * PLANE3 + off;
        *(float4*)(o2)          = eval4(g, tb + 6 * PIECES);
        *(float4*)(o2 + HW)     = eval4(g, tb + 7 * PIECES);
        *(float4*)(o2 + 2 * HW) = eval4(g, tb + 8 * PIECES);
    }

    // ===== reset counters for next graph replay =============================
    __threadfence();
    if (tid == 0) {
        if (atomicAdd(&g_done, 1u) == NBLK - 1u) {
            g_s1 = 0; g_s2 = 0; g_s3 = 0; g_s4 = 0; g_s5 = 0;
            __threadfence();
            g_done = 0;
        }
    }
}

// ---------------------------------------------------------------------------
extern "C" void kernel_launch(void* const* d_in, const int* in_sizes, int n_in,
                              void* d_out, int out_size) {
    const float* x       = (const float*)d_in[0];
    const float* f_feat  = (const float*)d_in[1];
    const float* b_feat  = (const float*)d_in[2];
    const float* pw1     = (const float*)d_in[3];
    const float* pb1     = (const float*)d_in[4];
    const float* pw2     = (const float*)d_in[5];
    const float* pb2     = (const float*)d_in[6];
    const float* fw1     = (const float*)d_in[7];
    const float* fb1     = (const float*)d_in[8];
    const float* fw2     = (const float*)d_in[9];
    const float* fb2     = (const float*)d_in[10];
    float* out = (float*)d_out;

    fused_kernel<<<NBLK, NTHR>>>(x, f_feat, b_feat, pw1, pb1, pw2, pb2,
                                 fw1, fb1, fw2, fb2, out);
}

// round 8
// speedup vs baseline: 1.0777x; 1.0777x over previous
#include <cuda_runtime.h>

#define B 8
#define HID 192
#define CATN 576
#define PIECES 64
#define HW 65536   // 256*256
#define PLANE3 (3*HW)
#define NBLK 296   // 2 blocks per SM, one co-resident wave
#define NTHR 256

// ---------------- scratch (__device__ globals; allocation-free rule) --------
__device__ float  g_p1[8][4*B*HID];   // stage1 partials [isplit][(k*B+b)*HID+o]
__device__ float  g_p2[4][B*CATN];    // stage2 partials [isplit][b*CATN+sec*HID+o]
__device__ float  g_p3[6][B*HID];     // stage3 partials
__device__ float  g_p4[4][B*HID];     // stage4 partials
__device__ float2 g_table[B*9*PIECES];
__device__ unsigned g_s1, g_s2, g_s3, g_s4, g_s5, g_done;   // zero-init

// ---------------- flag sync --------------------------------------------------
__device__ __forceinline__ void wait_flag(unsigned* c, unsigned n) {
    if (threadIdx.x == 0) {
        while (*(volatile unsigned*)c < n) __nanosleep(40);
        __threadfence();                 // acquire: drop stale L1
    }
    __syncthreads();
}
__device__ __forceinline__ void signal_flag(unsigned* c) {
    __threadfence();                     // release: drain stores to L2
    __syncthreads();
    if (threadIdx.x == 0) atomicAdd(c, 1u);
}

// ---------------- register-resident GEMV ------------------------------------
// lane l owns outputs obase+t*32+l; warp w owns reduction rows [w*CH, w*CH+CH)
template<int CH, int NT>
__device__ __forceinline__ void wload(float wreg[CH][NT], const float* __restrict__ W) {
    const int l = threadIdx.x & 31;
    const int w = threadIdx.x >> 5;
    const float* Wp = W + (w * CH) * HID + l;
    #pragma unroll
    for (int j = 0; j < CH; j++)
        #pragma unroll
        for (int t = 0; t < NT; t++)
            wreg[j][t] = Wp[j * HID + t * 32];
}

template<int CH, int NT, int RB>
__device__ __forceinline__ void gemv_reg(const float wreg[CH][NT],
                                         const float* __restrict__ sX,
                                         float acc[NT][B]) {
    const int w = threadIdx.x >> 5;
    #pragma unroll
    for (int j = 0; j < CH; j++)
        #pragma unroll
        for (int b = 0; b < B; b++) {
            float xv = sX[b * RB + w * CH + j];
            #pragma unroll
            for (int t = 0; t < NT; t++) acc[t][b] = fmaf(xv, wreg[j][t], acc[t][b]);
        }
}

template<int NT>
__device__ __forceinline__ void store_partials(float acc[NT][B], float* s_part,
                                               float* __restrict__ dst,
                                               int strideB, int obase) {
    const int OT = NT * 32;
    const int l = threadIdx.x & 31;
    const int w = threadIdx.x >> 5;
    #pragma unroll
    for (int t = 0; t < NT; t++)
        #pragma unroll
        for (int b = 0; b < B; b++)
            s_part[(w * B + b) * OT + t * 32 + l] = acc[t][b];
    __syncthreads();
    for (int p = threadIdx.x; p < OT * B; p += NTHR) {
        int b = p / OT, o = p % OT;
        float s = 0.0f;
        #pragma unroll
        for (int w2 = 0; w2 < 8; w2++) s += s_part[(w2 * B + b) * OT + o];
        dst[b * strideB + obase + o] = s;
    }
}

__device__ __forceinline__ void l2_prefetch(const void* p) {
    asm volatile("prefetch.global.L2 [%0];" :: "l"(p));
}

// ---------------- render helpers --------------------------------------------
__device__ __forceinline__ float evalp(float v, const float2* __restrict__ tab) {
    float s = v * 64.0f;
    int k = (int)s;
    k = min(k, 63);
    float frac = s - (float)k;
    float2 e = tab[k];
    return fmaf(frac, e.y, e.x);
}
__device__ __forceinline__ float4 eval4(float4 v, const float2* __restrict__ tab) {
    return make_float4(evalp(v.x, tab), evalp(v.y, tab), evalp(v.z, tab), evalp(v.w, tab));
}

// ---------------- the whole problem, one kernel -----------------------------
__global__ __launch_bounds__(NTHR, 2) void fused_kernel(
    const float* __restrict__ x,
    const float* __restrict__ f_feat, const float* __restrict__ b_feat,
    const float* __restrict__ pw1, const float* __restrict__ pb1,
    const float* __restrict__ pw2, const float* __restrict__ pb2,
    const float* __restrict__ fw1, const float* __restrict__ fb1,
    const float* __restrict__ fw2, const float* __restrict__ fb2,
    float* __restrict__ out)
{
    __shared__ __align__(16) float s_buf[9216];   // 36 KB, reused per phase
    float* s_x    = s_buf;                        // activations (<=768 floats)
    float* s_part = s_buf + 1536;                 // warp partials (<=6144)
    const int tid = threadIdx.x;
    const int blk = blockIdx.x;

    if (blk < 64) {
        // ===== stage 1: proj layer1. 64 blocks = 4k x 2oh x 8ip =============
        int k  = blk >> 4;
        int oh = (blk >> 3) & 1;
        int ip = blk & 7;
        int ibase = ip * 64, obase = oh * 96;
        float wreg[8][3];
        wload<8, 3>(wreg, pw1 + (k * 512 + ibase) * HID + obase);
        const float* feat = (k & 1) ? b_feat : f_feat;
        for (int idx = tid; idx < B * 64; idx += NTHR)
            s_x[idx] = feat[(idx >> 6) * 512 + ibase + (idx & 63)];
        __syncthreads();
        float acc[3][B];
        #pragma unroll
        for (int t = 0; t < 3; t++)
            #pragma unroll
            for (int b = 0; b < B; b++) acc[t][b] = 0.0f;
        gemv_reg<8, 3, 64>(wreg, s_x, acc);
        store_partials<3>(acc, s_part, g_p1[ip] + (k * B) * HID, HID, obase);
        signal_flag(&g_s1);

    } else if (blk < 88) {
        // ===== stage 2: proj layer2. 24 blocks = 3sec x 2oh x 4ip ===========
        int local = blk - 64;
        int sec = local >> 3;
        int oh  = (local >> 2) & 1;
        int ip  = local & 3;
        int ibase = ip * 48, obase = oh * 96;
        int k0 = (sec == 2) ? 2 : sec;
        float wregA[6][3], wregB[6][3];
        wload<6, 3>(wregA, pw2 + (k0 * HID + ibase) * HID + obase);
        if (sec == 2)
            wload<6, 3>(wregB, pw2 + (3 * HID + ibase) * HID + obase);

        wait_flag(&g_s1, 64);
        int nk = (sec == 2) ? 2 : 1;
        for (int kk = 0; kk < nk; kk++) {
            int k = (sec == 2) ? (2 + kk) : sec;
            for (int idx = tid; idx < B * 48; idx += NTHR) {
                int b = idx / 48, i = idx % 48;
                int gi = (k * B + b) * HID + ibase + i;
                float v = g_p1[0][gi] + g_p1[1][gi] + g_p1[2][gi] + g_p1[3][gi]
                        + g_p1[4][gi] + g_p1[5][gi] + g_p1[6][gi] + g_p1[7][gi]
                        + pb1[k * HID + ibase + i];
                s_x[kk * B * 48 + idx] = fmaxf(v, 0.0f);
            }
        }
        __syncthreads();
        float acc[3][B];
        #pragma unroll
        for (int t = 0; t < 3; t++)
            #pragma unroll
            for (int b = 0; b < B; b++) acc[t][b] = 0.0f;
        gemv_reg<6, 3, 48>(wregA, s_x, acc);
        if (sec == 2) gemv_reg<6, 3, 48>(wregB, s_x + B * 48, acc);
        store_partials<3>(acc, s_part, g_p2[ip], CATN, sec * HID + obase);
        signal_flag(&g_s2);

    } else if (blk < 106) {
        // ===== stage 3: fc layer1. 18 blocks = 3oq x 6ip ====================
        int local = blk - 88;
        int oq = local / 6, ip = local % 6;
        int ibase = ip * 96, obase = oq * 64;       // ibase over CATN
        int sec = ip >> 1, off = (ip & 1) * 96;
        float wreg[12][2];
        wload<12, 2>(wreg, fw1 + ibase * HID + obase);

        wait_flag(&g_s2, 24);
        for (int idx = tid; idx < B * 96; idx += NTHR) {
            int b = idx / 96, i = idx % 96;
            int gi = b * CATN + ibase + i;
            float v = g_p2[0][gi] + g_p2[1][gi] + g_p2[2][gi] + g_p2[3][gi];
            v += (sec < 2) ? pb2[sec * HID + off + i]
                           : (pb2[2 * HID + off + i] + pb2[3 * HID + off + i]);
            s_x[idx] = v;
        }
        __syncthreads();
        float acc[2][B];
        #pragma unroll
        for (int t = 0; t < 2; t++)
            #pragma unroll
            for (int b = 0; b < B; b++) acc[t][b] = 0.0f;
        gemv_reg<12, 2, 96>(wreg, s_x, acc);
        store_partials<2>(acc, s_part, g_p3[ip], HID, obase);
        signal_flag(&g_s3);

    } else if (blk < 114) {
        // ===== stage 4: fc layer2. 8 blocks = 2oh x 4ip =====================
        int local = blk - 106;
        int oh = local >> 2, ip = local & 3;
        int ibase = ip * 48, obase = oh * 96;
        float wreg[6][3];
        wload<6, 3>(wreg, fw2 + ibase * HID + obase);

        wait_flag(&g_s3, 18);
        for (int idx = tid; idx < B * 48; idx += NTHR) {
            int b = idx / 48, i = idx % 48;
            int gi = b * HID + ibase + i;
            float v = g_p3[0][gi] + g_p3[1][gi] + g_p3[2][gi]
                    + g_p3[3][gi] + g_p3[4][gi] + g_p3[5][gi] + fb1[ibase + i];
            s_x[idx] = fmaxf(v, 0.0f);
        }
        __syncthreads();
        float acc[3][B];
        #pragma unroll
        for (int t = 0; t < 3; t++)
            #pragma unroll
            for (int b = 0; b < B; b++) acc[t][b] = 0.0f;
        gemv_reg<6, 3, 48>(wreg, s_x, acc);
        store_partials<3>(acc, s_part, g_p4[ip], HID, obase);
        signal_flag(&g_s4);

    } else if (blk < 123) {
        // ===== stage 5: lookup tables. 9 blocks x 8 warps ===================
        wait_flag(&g_s4, 8);
        int l = tid & 31;
        int grp = (blk - 114) * 8 + (tid >> 5);    // 0..71
        int set = grp / 24;
        int b   = (grp % 24) / 3;
        int c   = grp % 3;
        int e0 = 2 * l, e1 = 2 * l + 1;
        float v0, v1;
        if (set == 0) {
            int gi = b * HID + c * 64;
            v0 = g_p4[0][gi + e0] + g_p4[1][gi + e0] + g_p4[2][gi + e0]
               + g_p4[3][gi + e0] + fb2[c * 64 + e0];
            v1 = g_p4[0][gi + e1] + g_p4[1][gi + e1] + g_p4[2][gi + e1]
               + g_p4[3][gi + e1] + fb2[c * 64 + e1];
        } else {
            int sec = set - 1;                     // param_f=0, param_b=1
            int gi = b * CATN + sec * HID + c * 64;
            v0 = g_p2[0][gi + e0] + g_p2[1][gi + e0] + g_p2[2][gi + e0]
               + g_p2[3][gi + e0] + pb2[sec * HID + c * 64 + e0];
            v1 = g_p2[0][gi + e1] + g_p2[1][gi + e1] + g_p2[2][gi + e1]
               + g_p2[3][gi + e1] + pb2[sec * HID + c * 64 + e1];
        }
        float pair = v0 + v1;
        float inc = pair;
        #pragma unroll
        for (int d = 1; d < 32; d <<= 1) {
            float u = __shfl_up_sync(0xffffffffu, inc, d);
            if (l >= d) inc += u;
        }
        float total = __shfl_sync(0xffffffffu, inc, 31);
        float excl  = inc - pair;
        float inv   = 1.0f / (total + 1e-30f);
        float2* t = &g_table[(b * 9 + set * 3 + c) * PIECES];
        t[e0] = make_float2(excl * inv, v0 * inv);
        t[e1] = make_float2((excl + v0) * inv, v1 * inv);
        signal_flag(&g_s5);

    } else {
        // ===== 173 idle blocks: warm L2 with x while the MLP chain runs =====
        for (int i = (blk - 123) * NTHR + tid; i < (B * PLANE3) / 32; i += 173 * NTHR)
            l2_prefetch(x + i * 32);
    }

    // ===== final: render (everyone waits for tables) ========================
    wait_flag(&g_s5, 9);
    float2* s_tab = (float2*)s_buf;               // 72 tables = 36 KB
    for (int i = tid; i < B * 9 * PIECES; i += NTHR) s_tab[i] = g_table[i];
    __syncthreads();

    int gtid = blk * NTHR + tid;
    for (int p = gtid; p < B * HW / 4; p += NBLK * NTHR) {
        int b   = p >> 14;                        // HW/4 = 16384 per batch
        int off = (p & 16383) << 2;
        const float* xb = x + b * PLANE3 + off;
        float4 v0 = *(const float4*)(xb);
        float4 v1 = *(const float4*)(xb + HW);
        float4 v2 = *(const float4*)(xb + 2 * HW);

        float4 g;
        g.x = fmaf(0.114f, v2.x, fmaf(0.587f, v1.x, 0.299f * v0.x));
        g.y = fmaf(0.114f, v2.y, fmaf(0.587f, v1.y, 0.299f * v0.y));
        g.z = fmaf(0.114f, v2.z, fmaf(0.587f, v1.z, 0.299f * v0.z));
        g.w = fmaf(0.114f, v2.w, fmaf(0.587f, v1.w, 0.299f * v0.w));

        const float2* tb = s_tab + b * 9 * PIECES;

        float* o0 = out + b * PLANE3 + off;
        *(float4*)(o0)          = eval4(v0, tb + 0 * PIECES);
        *(float4*)(o0 + HW)     = eval4(v1, tb + 1 * PIECES);
        *(float4*)(o0 + 2 * HW) = eval4(v2, tb + 2 * PIECES);

        float* o1 = out + B * PLANE3 + b * PLANE3 + off;
        *(float4*)(o1)          = eval4(g, tb + 3 * PIECES);
        *(float4*)(o1 + HW)     = eval4(g, tb + 4 * PIECES);
        *(float4*)(o1 + 2 * HW) = eval4(g, tb + 5 * PIECES);

        float* o2 = out + 2 * B * PLANE3 + b * PLANE3 + off;
        *(float4*)(o2)          = eval4(g, tb + 6 * PIECES);
        *(float4*)(o2 + HW)     = eval4(g, tb + 7 * PIECES);
        *(float4*)(o2 + 2 * HW) = eval4(g, tb + 8 * PIECES);
    }

    // ===== reset counters for next graph replay =============================
    __threadfence();
    if (tid == 0) {
        if (atomicAdd(&g_done, 1u) == NBLK - 1u) {
            g_s1 = 0; g_s2 = 0; g_s3 = 0; g_s4 = 0; g_s5 = 0;
            __threadfence();
            g_done = 0;
        }
    }
}

// ---------------------------------------------------------------------------
extern "C" void kernel_launch(void* const* d_in, const int* in_sizes, int n_in,
                              void* d_out, int out_size) {
    const float* x       = (const float*)d_in[0];
    const float* f_feat  = (const float*)d_in[1];
    const float* b_feat  = (const float*)d_in[2];
    const float* pw1     = (const float*)d_in[3];
    const float* pb1     = (const float*)d_in[4];
    const float* pw2     = (const float*)d_in[5];
    const float* pb2     = (const float*)d_in[6];
    const float* fw1     = (const float*)d_in[7];
    const float* fb1     = (const float*)d_in[8];
    const float* fw2     = (const float*)d_in[9];
    const float* fb2     = (const float*)d_in[10];
    float* out = (float*)d_out;

    fused_kernel<<<NBLK, NTHR>>>(x, f_feat, b_feat, pw1, pb1, pw2, pb2,
                                 fw1, fb1, fw2, fb2, out);
}